// round 11
// baseline (speedup 1.0000x reference)
#include <cuda_runtime.h>
#include <cuda_fp16.h>
#include <cstdint>

// ---------------------------------------------------------------------------
// Problem:
//   Ec : (128 chan, 256 s, 3 l, 128 d) f32
//   W1 : (6,128,128,1,128)  W2 : (5,128,128,2,128)  W3 : (5,128,128,3,128)
//   b1 : (6,128) b2 : (5,128) b3 : (5,128)
//   out: (128 o, 256 s, 1, 16 k) f32
// 33 conv maps: z<18 -> h=1 (kl=z/3, p=z%3); z<28 -> h=2; else h=3.
// GEMM per map: out[o,s] = sum_{a,c,d} Ec[a,s,p+c,d] * W[kl,o,a,c,d]
//   M=256(s), N=128(o), K=128*h*128.
// R10: f16-ACCUMULATE mma.sync experiment (possible 2x rate vs f32-accum).
// f16 accumulators live one k64 stage (4 MMAs), spilled to f32 regs each
// stage -> added rel_err ~4.5e-4, total ~5.5e-4 < 1e-3.
// Producers (warps 8-9) now feed BOTH A (cp.async fp16) and B (LDG f32 ->
// cvt -> STS); consumers only ldmatrix+MMA+spill.
// ---------------------------------------------------------------------------

#define NMAPS 33
#define SLOT_STRIDE 24            // max chunks per map = 8*h <= 24
__device__ __half g_ecH[12582912];                      // Ec fp16 (25 MB)
__device__ float  g_part[NMAPS * SLOT_STRIDE * 32768];  // split-K partials

#define PITCH 144                 // smem row pitch: 128B fp16 data + 16B pad
#define OFF_A 0                   // A: 256 rows (s)
#define OFF_B (256 * PITCH)       // B: 128 rows (o)
#define STAGE_BYTES (384 * PITCH) // 55296
#define NSTAGE 3
#define SMEM_BYTES (NSTAGE * STAGE_BYTES)      // 165888
#define NTHREADS 320              // 8 consumer warps + 2 producer warps
#define NST 32                    // k64 stages per K=2048 chunk

// ---------------------------------------------------------------------------
__device__ __forceinline__ uint32_t smem_u32(const void* p) {
    uint32_t r;
    asm("{ .reg .u64 t; cvta.to.shared.u64 t, %1; cvt.u32.u64 %0, t; }"
        : "=r"(r) : "l"(p));
    return r;
}

__device__ __forceinline__ void ldm4(uint32_t (&r)[4], uint32_t addr) {
    asm volatile("ldmatrix.sync.aligned.m8n8.x4.shared.b16 {%0,%1,%2,%3}, [%4];"
        : "=r"(r[0]), "=r"(r[1]), "=r"(r[2]), "=r"(r[3]) : "r"(addr));
}

// fp16-accumulate MMA: D(f16x2 pair) = A*B + C
__device__ __forceinline__ void mma_f16acc(uint32_t (&d)[2],
                                           const uint32_t (&a)[4],
                                           uint32_t b0, uint32_t b1) {
    asm volatile(
        "mma.sync.aligned.m16n8k16.row.col.f16.f16.f16.f16 "
        "{%0,%1}, {%2,%3,%4,%5}, {%6,%7}, {%0,%1};"
        : "+r"(d[0]), "+r"(d[1])
        : "r"(a[0]), "r"(a[1]), "r"(a[2]), "r"(a[3]), "r"(b0), "r"(b1));
}

__device__ __forceinline__ void cpa16(uint32_t dst, const void* src) {
    asm volatile("cp.async.cg.shared.global [%0], [%1], 16;"
        :: "r"(dst), "l"(src));
}
#define CPA_COMMIT() asm volatile("cp.async.commit_group;" ::: "memory")
#define CPA_WAIT1()  asm volatile("cp.async.wait_group 1;"  ::: "memory")

// f32x4 -> fp16x4 (8 bytes)
__device__ __forceinline__ uint2 cvt4(float4 v) {
    __half2 h01 = __floats2half2_rn(v.x, v.y);
    __half2 h23 = __floats2half2_rn(v.z, v.w);
    uint2 r;
    r.x = *reinterpret_cast<uint32_t*>(&h01);
    r.y = *reinterpret_cast<uint32_t*>(&h23);
    return r;
}

// ---------------------------------------------------------------------------
// Ec f32 -> fp16 (one small pass; A is reused by all 33 maps)
// ---------------------------------------------------------------------------
__global__ void vrtconv_cvt_ec(const float4* __restrict__ src, int n4)
{
    uint2* dst = reinterpret_cast<uint2*>(g_ecH);
    for (int i = blockIdx.x * blockDim.x + threadIdx.x; i < n4;
         i += gridDim.x * blockDim.x)
        dst[i] = cvt4(src[i]);
}

// ---------------------------------------------------------------------------
// GEMM: grid(424). One CTA = one map z, one K-chunk of 16 (a,c) pairs
// (K=2048), full M=256(s), full N=128(o). 32 stages of k64, 3-buffer ring.
// Consumers (warps 0-7, tile 64x64): ldmatrix + f16-acc MMA + f32 spill.
// Producers (warps 8-9): A via cp.async (fp16), B via LDG f32 + cvt + STS.
// ---------------------------------------------------------------------------
__global__ __launch_bounds__(NTHREADS, 1)
void vrtconv_gemm(const float* __restrict__ W1, const float* __restrict__ W2,
                  const float* __restrict__ W3)
{
    extern __shared__ char smem[];
    const int tid  = threadIdx.x;
    const int lane = tid & 31;
    const int wid  = tid >> 5;
    const bool consumer = (wid < 8);
    const uint32_t sb = smem_u32(smem);

    // job decode: j -> (z, chunk, h)
    const int j = blockIdx.x;
    int z, chunk, h;
    if (j < 144)      { z = j >> 3;                  chunk = j & 7;    h = 1; }
    else if (j < 304) { int t = j - 144; z = 18 + (t >> 4); chunk = t & 15; h = 2; }
    else              { int t = j - 304; z = 28 + t / 24;   chunk = t % 24; h = 3; }

    int kl, p; const float* W;
    if (h == 1)      { kl = z / 3;         p = z % 3;        W = W1; }
    else if (h == 2) { kl = (z - 18) >> 1; p = (z - 18) & 1; W = W2; }
    else             { kl = z - 28;        p = 0;            W = W3; }

    const size_t oStride = (size_t)16384 * h;        // o-stride in W (f32)
    const float* Wk = W + (size_t)kl * 2097152 * (size_t)h;
    const __half* ecH = g_ecH;

    if (consumer) {
        // ---------------- consumer warps: pure MMA ------------------------
        const int wm = wid & 3;      // 4 m-warps (64 s each)
        const int wn = wid >> 2;     // 2 n-warps (64 o each)

        float acc[4][8][4];
        #pragma unroll
        for (int a = 0; a < 4; ++a)
            #pragma unroll
            for (int b = 0; b < 8; ++b)
                #pragma unroll
                for (int c = 0; c < 4; ++c) acc[a][b][c] = 0.0f;

        const uint32_t aByte = (uint32_t)((wm * 64 + (lane & 15)) * PITCH
                                          + (lane >> 4) * 16);
        const uint32_t bByte = (uint32_t)((wn * 64 + (lane & 15)) * PITCH
                                          + (lane >> 4) * 16);

        for (int st = 0; st < NST; ++st) {
            __syncthreads();                        // stage st (A & B) ready
            const uint32_t bufb = sb + (uint32_t)((st % 3) * STAGE_BYTES);

            #pragma unroll
            for (int mh = 0; mh < 2; ++mh) {        // two m-halves (regs)
                uint32_t facc[2][8][2];
                #pragma unroll
                for (int m2 = 0; m2 < 2; ++m2)
                    #pragma unroll
                    for (int n8 = 0; n8 < 8; ++n8) {
                        facc[m2][n8][0] = 0u; facc[m2][n8][1] = 0u;
                    }

                #pragma unroll
                for (int kk = 0; kk < 4; ++kk) {    // k64 = 4 x k16
                    uint32_t af[2][4], bf[4][4];
                    #pragma unroll
                    for (int m2 = 0; m2 < 2; ++m2)
                        ldm4(af[m2], bufb + OFF_A + aByte
                             + (mh * 2 + m2) * (16 * PITCH) + kk * 32);
                    #pragma unroll
                    for (int nj = 0; nj < 4; ++nj)
                        ldm4(bf[nj], bufb + OFF_B + bByte
                             + nj * (16 * PITCH) + kk * 32);
                    #pragma unroll
                    for (int m2 = 0; m2 < 2; ++m2)
                        #pragma unroll
                        for (int nj = 0; nj < 4; ++nj) {
                            mma_f16acc(facc[m2][nj * 2],     af[m2],
                                       bf[nj][0], bf[nj][2]);
                            mma_f16acc(facc[m2][nj * 2 + 1], af[m2],
                                       bf[nj][1], bf[nj][3]);
                        }
                }

                // spill f16 segment -> f32 accumulators
                #pragma unroll
                for (int m2 = 0; m2 < 2; ++m2)
                    #pragma unroll
                    for (int n8 = 0; n8 < 8; ++n8) {
                        __half2 h0 = *reinterpret_cast<__half2*>(&facc[m2][n8][0]);
                        __half2 h1 = *reinterpret_cast<__half2*>(&facc[m2][n8][1]);
                        float2 f0 = __half22float2(h0);
                        float2 f1 = __half22float2(h1);
                        float* a4 = acc[mh * 2 + m2][n8];
                        a4[0] += f0.x; a4[1] += f0.y;
                        a4[2] += f1.x; a4[3] += f1.y;
                    }
            }
        }

        // epilogue: partials [map][chunk][o:128][s:256]
        float* dst = g_part + ((size_t)z * SLOT_STRIDE + chunk) * 32768;
        #pragma unroll
        for (int mt = 0; mt < 4; ++mt) {
            const int s0 = wm * 64 + mt * 16 + (lane >> 2);
            #pragma unroll
            for (int n8 = 0; n8 < 8; ++n8) {
                const int o = wn * 64 + n8 * 8 + (lane & 3) * 2;
                dst[(size_t)o * 256 + s0]           = acc[mt][n8][0];
                dst[(size_t)(o + 1) * 256 + s0]     = acc[mt][n8][1];
                dst[(size_t)o * 256 + s0 + 8]       = acc[mt][n8][2];
                dst[(size_t)(o + 1) * 256 + s0 + 8] = acc[mt][n8][3];
            }
        }
    } else {
        // ------------- producer warps: A (cp.async) + B (f32->fp16) -------
        const int ptid = tid - 256;               // 0..63

        auto cpaA = [&](int st) {
            const int q = chunk * 16 + (st >> 1);
            int a, cl;
            if (h == 1)      { a = q;      cl = 0;     }
            else if (h == 2) { a = q >> 1; cl = q & 1; }
            else             { a = q / 3;  cl = q % 3; }
            const int d0 = (st & 1) * 64;
            const __half* src = ecH + (size_t)a * 98304
                              + (size_t)(p + cl) * 128 + d0;
            const uint32_t sa = sb + (uint32_t)((st % 3) * STAGE_BYTES) + OFF_A;
            #pragma unroll
            for (int i = 0; i < 32; ++i) {         // 256 rows x 8 x 16B / 64
                const int flat = i * 64 + ptid;
                const int row = flat >> 3, c = flat & 7;
                cpa16(sa + row * PITCH + c * 16,
                      src + (size_t)row * 384 + c * 8);
            }
        };

        // B stage: 128 rows x 64 f32 = 2048 float4; two rounds of 16/thread
        auto ldgstB = [&](int st) {
            const int q  = chunk * 16 + (st >> 1);
            const int d0 = (st & 1) * 64;
            const float* src = Wk + (size_t)q * 128 + d0;
            char* base = smem + (st % 3) * STAGE_BYTES + OFF_B;
            #pragma unroll
            for (int rnd = 0; rnd < 2; ++rnd) {
                float4 bs[16];
                #pragma unroll
                for (int i = 0; i < 16; ++i) {
                    const int flat = rnd * 1024 + i * 64 + ptid;
                    const int row = flat >> 4, c4 = flat & 15;
                    bs[i] = *reinterpret_cast<const float4*>(
                        src + (size_t)row * oStride + c4 * 4);
                }
                #pragma unroll
                for (int i = 0; i < 16; ++i) {
                    const int flat = rnd * 1024 + i * 64 + ptid;
                    const int row = flat >> 4, c4 = flat & 15;
                    *reinterpret_cast<uint2*>(base + row * PITCH + c4 * 8)
                        = cvt4(bs[i]);
                }
            }
        };

        // prologue: A(0), A(1) in flight; B(0) staged; A(0) landed
        cpaA(0); CPA_COMMIT();
        cpaA(1); CPA_COMMIT();
        ldgstB(0);
        CPA_WAIT1();                               // A(0) complete

        for (int st = 0; st < NST; ++st) {
            __syncthreads();                       // release stage st
            if (st + 1 < NST) ldgstB(st + 1);
            if (st + 2 < NST) { cpaA(st + 2); CPA_COMMIT(); }
            CPA_WAIT1();                           // A(st+1) complete
        }
    }
}

// ---------------------------------------------------------------------------
// Fused reduce: sum 8h chunks per map, + bias, max over p, ReLU,
// write (o, s, 1, 16). Reads each partial exactly once (55.6 MB).
// ---------------------------------------------------------------------------
__global__ void vrtconv_finish(const float* __restrict__ b1,
                               const float* __restrict__ b2,
                               const float* __restrict__ b3,
                               float* __restrict__ out)
{
    const int t = blockIdx.x * blockDim.x + threadIdx.x;   // 32768 threads
    const int o = t >> 8;
    const int s = t & 255;

    float res[16];
    #pragma unroll
    for (int h_idx = 0; h_idx < 3; ++h_idx) {
        const int P    = 3 - h_idx;
        const int cnt  = (h_idx == 0) ? 6 : 5;
        const int base = (h_idx == 0) ? 0 : (h_idx == 1 ? 18 : 28);
        const int nch  = 8 * (h_idx + 1);
        const float* bb = (h_idx == 0) ? b1 : (h_idx == 1 ? b2 : b3);
        for (int jj = 0; jj < cnt; ++jj) {
            const float bias = bb[jj * 128 + o];
            float m = -1e30f;
            for (int pp = 0; pp < P; ++pp) {
                const int zmap = base + jj * P + pp;
                const float* q = g_part + ((size_t)zmap * SLOT_STRIDE) * 32768
                               + (size_t)o * 256 + s;
                float sum = 0.0f;
                #pragma unroll 8
                for (int cc = 0; cc < nch; ++cc) sum += q[(size_t)cc * 32768];
                m = fmaxf(m, sum + bias);
            }
            res[h_idx + 3 * jj] = fmaxf(m, 0.0f);
        }
    }

    float4* po = reinterpret_cast<float4*>(out + ((size_t)o * 256 + s) * 16);
    po[0] = make_float4(res[0],  res[1],  res[2],  res[3]);
    po[1] = make_float4(res[4],  res[5],  res[6],  res[7]);
    po[2] = make_float4(res[8],  res[9],  res[10], res[11]);
    po[3] = make_float4(res[12], res[13], res[14], res[15]);
}

// ---------------------------------------------------------------------------
extern "C" void kernel_launch(void* const* d_in, const int* in_sizes, int n_in,
                              void* d_out, int out_size) {
    const float* Ec = (const float*)d_in[0];
    const float* W1 = (const float*)d_in[1];
    const float* W2 = (const float*)d_in[2];
    const float* W3 = (const float*)d_in[3];
    const float* b1 = (const float*)d_in[4];
    const float* b2 = (const float*)d_in[5];
    const float* b3 = (const float*)d_in[6];
    float* out = (float*)d_out;

    vrtconv_cvt_ec<<<1536, 256>>>((const float4*)Ec, 12582912 / 4);

    cudaFuncSetAttribute(vrtconv_gemm,
                         cudaFuncAttributeMaxDynamicSharedMemorySize, SMEM_BYTES);
    vrtconv_gemm<<<424, NTHREADS, SMEM_BYTES>>>(W1, W2, W3);

    vrtconv_finish<<<128, 256>>>(b1, b2, b3, out);
}

// round 12
// speedup vs baseline: 1.0165x; 1.0165x over previous
#include <cuda_runtime.h>
#include <cuda_fp16.h>
#include <cstdint>

// ---------------------------------------------------------------------------
// Problem:
//   Ec : (128 chan, 256 s, 3 l, 128 d) f32
//   W1 : (6,128,128,1,128)  W2 : (5,128,128,2,128)  W3 : (5,128,128,3,128)
//   b1 : (6,128) b2 : (5,128) b3 : (5,128)
//   out: (128 o, 256 s, 1, 16 k) f32
// 33 conv maps: z<18 -> h=1 (kl=z/3, p=z%3); z<28 -> h=2; else h=3.
// GEMM per map: out[o,s] = sum_{a,c,d} Ec[a,s,p+c,d] * W[kl,o,a,c,d]
//   M=256(s), N=128(o), K=128*h*128.
// R11 = R9 (best: 243.6us) with the Ec fp16 pre-pass folded into the GEMM:
// producer warps 8-9 now feed BOTH A (Ec f32 -> fp16) and B (W f32 -> fp16)
// with a 2-deep software pipeline over 6 load/convert/store rounds per stage.
// Consumers (warps 0-7) are pure ldmatrix + mma.sync f32-acc (rt~16/SMSP).
// Single-kernel GEMM + fused reduce; two launches total.
// ---------------------------------------------------------------------------

#define NMAPS 33
#define SLOT_STRIDE 24            // max chunks per map = 8*h <= 24
__device__ float g_part[NMAPS * SLOT_STRIDE * 32768];   // split-K partials

#define PITCH 144                 // smem row pitch: 128B fp16 data + 16B pad
#define OFF_A 0                   // A: 256 rows (s)
#define OFF_B (256 * PITCH)       // B: 128 rows (o)
#define STAGE_BYTES (384 * PITCH) // 55296
#define NSTAGE 3
#define SMEM_BYTES (NSTAGE * STAGE_BYTES)      // 165888
#define NTHREADS 320              // 8 consumer warps + 2 producer warps
#define NST 32                    // k64 stages per K=2048 chunk

// ---------------------------------------------------------------------------
__device__ __forceinline__ uint32_t smem_u32(const void* p) {
    uint32_t r;
    asm("{ .reg .u64 t; cvta.to.shared.u64 t, %1; cvt.u32.u64 %0, t; }"
        : "=r"(r) : "l"(p));
    return r;
}

__device__ __forceinline__ void ldm4(uint32_t (&r)[4], uint32_t addr) {
    asm volatile("ldmatrix.sync.aligned.m8n8.x4.shared.b16 {%0,%1,%2,%3}, [%4];"
        : "=r"(r[0]), "=r"(r[1]), "=r"(r[2]), "=r"(r[3]) : "r"(addr));
}

__device__ __forceinline__ void mma_fp16(float (&d)[4], const uint32_t (&a)[4],
                                         uint32_t b0, uint32_t b1) {
    asm volatile(
        "mma.sync.aligned.m16n8k16.row.col.f32.f16.f16.f32 "
        "{%0,%1,%2,%3}, {%4,%5,%6,%7}, {%8,%9}, {%0,%1,%2,%3};"
        : "+f"(d[0]), "+f"(d[1]), "+f"(d[2]), "+f"(d[3])
        : "r"(a[0]), "r"(a[1]), "r"(a[2]), "r"(a[3]), "r"(b0), "r"(b1));
}

// f32x4 -> fp16x4 (8 bytes)
__device__ __forceinline__ uint2 cvt4(float4 v) {
    __half2 h01 = __floats2half2_rn(v.x, v.y);
    __half2 h23 = __floats2half2_rn(v.z, v.w);
    uint2 r;
    r.x = *reinterpret_cast<uint32_t*>(&h01);
    r.y = *reinterpret_cast<uint32_t*>(&h23);
    return r;
}

// ---------------------------------------------------------------------------
// GEMM: grid(424). One CTA = one map z, one K-chunk of 16 (a,c) pairs
// (K=2048), full M=256(s), full N=128(o). 32 stages of k64, 3-buffer ring.
// Consumers (warps 0-7): warp tile 64x64, ldmatrix + mma.
// Producers (warps 8-9): stage-ahead A+B feed (LDG.128 f32 + cvt + STS),
// 6 rounds x 16 float4 per thread, 2-deep round pipeline.
// ---------------------------------------------------------------------------
__global__ __launch_bounds__(NTHREADS, 1)
void vrtconv_gemm(const float* __restrict__ Ec,
                  const float* __restrict__ W1, const float* __restrict__ W2,
                  const float* __restrict__ W3)
{
    extern __shared__ char smem[];
    const int tid  = threadIdx.x;
    const int lane = tid & 31;
    const int wid  = tid >> 5;
    const bool consumer = (wid < 8);
    const uint32_t sb = smem_u32(smem);

    // job decode: j -> (z, chunk, h)
    const int j = blockIdx.x;
    int z, chunk, h;
    if (j < 144)      { z = j >> 3;                  chunk = j & 7;    h = 1; }
    else if (j < 304) { int t = j - 144; z = 18 + (t >> 4); chunk = t & 15; h = 2; }
    else              { int t = j - 304; z = 28 + t / 24;   chunk = t % 24; h = 3; }

    int kl, p; const float* W;
    if (h == 1)      { kl = z / 3;         p = z % 3;        W = W1; }
    else if (h == 2) { kl = (z - 18) >> 1; p = (z - 18) & 1; W = W2; }
    else             { kl = z - 28;        p = 0;            W = W3; }

    const size_t oStride = (size_t)16384 * h;        // o-stride in W (f32)
    const float* Wk = W + (size_t)kl * 2097152 * (size_t)h;

    if (consumer) {
        // ---------------- consumer warps: pure MMA pipeline ----------------
        const int wm = wid & 3;      // 4 m-warps (64 s each)
        const int wn = wid >> 2;     // 2 n-warps (64 o each)

        float acc[4][8][4];
        #pragma unroll
        for (int a = 0; a < 4; ++a)
            #pragma unroll
            for (int b = 0; b < 8; ++b)
                #pragma unroll
                for (int c = 0; c < 4; ++c) acc[a][b][c] = 0.0f;

        const uint32_t aByte = (uint32_t)((wm * 64 + (lane & 15)) * PITCH
                                          + (lane >> 4) * 16);
        const uint32_t bByte = (uint32_t)((wn * 64 + (lane & 15)) * PITCH
                                          + (lane >> 4) * 16);

        for (int st = 0; st < NST; ++st) {
            __syncthreads();                       // stage st (A & B) ready

            const uint32_t bufb = sb + (uint32_t)((st % 3) * STAGE_BYTES);
            #pragma unroll
            for (int kk = 0; kk < 4; ++kk) {       // k64 = 4 x k16
                uint32_t af[4][4], bf[4][4];
                #pragma unroll
                for (int mt = 0; mt < 4; ++mt)
                    ldm4(af[mt], bufb + OFF_A + aByte + mt * (16 * PITCH) + kk * 32);
                #pragma unroll
                for (int nj = 0; nj < 4; ++nj)
                    ldm4(bf[nj], bufb + OFF_B + bByte + nj * (16 * PITCH) + kk * 32);
                #pragma unroll
                for (int mt = 0; mt < 4; ++mt)
                    #pragma unroll
                    for (int nj = 0; nj < 4; ++nj) {
                        mma_fp16(acc[mt][nj * 2],     af[mt], bf[nj][0], bf[nj][2]);
                        mma_fp16(acc[mt][nj * 2 + 1], af[mt], bf[nj][1], bf[nj][3]);
                    }
            }
        }

        // epilogue: partials [map][chunk][o:128][s:256]
        float* dst = g_part + ((size_t)z * SLOT_STRIDE + chunk) * 32768;
        #pragma unroll
        for (int mt = 0; mt < 4; ++mt) {
            const int s0 = wm * 64 + mt * 16 + (lane >> 2);
            #pragma unroll
            for (int n8 = 0; n8 < 8; ++n8) {
                const int o = wn * 64 + n8 * 8 + (lane & 3) * 2;
                dst[(size_t)o * 256 + s0]           = acc[mt][n8][0];
                dst[(size_t)(o + 1) * 256 + s0]     = acc[mt][n8][1];
                dst[(size_t)o * 256 + s0 + 8]       = acc[mt][n8][2];
                dst[(size_t)(o + 1) * 256 + s0 + 8] = acc[mt][n8][3];
            }
        }
    } else {
        // -------- producer warps: A (Ec f32) + B (W f32) -> fp16 smem ------
        const int ptid = tid - 256;               // 0..63

        // stage st: pair q = chunk*16 + (st>>1), d-block d0 = (st&1)*64
        // rounds 0..3: A (256 rows x 16 float4); rounds 4..5: B (128 x 16)
        auto produce = [&](int st) {
            const int q  = chunk * 16 + (st >> 1);
            const int d0 = (st & 1) * 64;
            int a, cl;
            if (h == 1)      { a = q;      cl = 0;     }
            else if (h == 2) { a = q >> 1; cl = q & 1; }
            else             { a = q / 3;  cl = q % 3; }
            const float* Asrc = Ec + (size_t)a * 98304
                              + (size_t)(p + cl) * 128 + d0;
            const float* Bsrc = Wk + (size_t)q * 128 + d0;
            char* base = smem + (st % 3) * STAGE_BYTES;

            float4 buf[2][16];
            // 2-deep pipeline across 6 rounds: load r, store r-1
            #pragma unroll
            for (int r = 0; r <= 6; ++r) {
                if (r < 6) {
                    float4* bb = buf[r & 1];
                    if (r < 4) {                   // A round
                        #pragma unroll
                        for (int i = 0; i < 16; ++i) {
                            const int flat = r * 1024 + i * 64 + ptid;
                            const int row = flat >> 4, c4 = flat & 15;
                            bb[i] = *reinterpret_cast<const float4*>(
                                Asrc + (size_t)row * 384 + c4 * 4);
                        }
                    } else {                       // B round
                        #pragma unroll
                        for (int i = 0; i < 16; ++i) {
                            const int flat = (r - 4) * 1024 + i * 64 + ptid;
                            const int row = flat >> 4, c4 = flat & 15;
                            bb[i] = *reinterpret_cast<const float4*>(
                                Bsrc + (size_t)row * oStride + c4 * 4);
                        }
                    }
                }
                if (r > 0) {
                    const int rp = r - 1;
                    float4* bb = buf[rp & 1];
                    const int off = (rp < 4) ? OFF_A : OFF_B;
                    const int rr  = (rp < 4) ? rp : rp - 4;
                    #pragma unroll
                    for (int i = 0; i < 16; ++i) {
                        const int flat = rr * 1024 + i * 64 + ptid;
                        const int row = flat >> 4, c4 = flat & 15;
                        *reinterpret_cast<uint2*>(base + off + row * PITCH + c4 * 8)
                            = cvt4(bb[i]);
                    }
                }
            }
        };

        // prologue: stage 0 fully staged before first barrier
        produce(0);

        for (int st = 0; st < NST; ++st) {
            __syncthreads();                       // pairs with consumer barrier
            if (st + 1 < NST) produce(st + 1);
        }
    }
}

// ---------------------------------------------------------------------------
// Fused reduce: sum 8h chunks per map, + bias, max over p, ReLU,
// write (o, s, 1, 16). Reads each partial exactly once (55.6 MB).
// ---------------------------------------------------------------------------
__global__ void vrtconv_finish(const float* __restrict__ b1,
                               const float* __restrict__ b2,
                               const float* __restrict__ b3,
                               float* __restrict__ out)
{
    const int t = blockIdx.x * blockDim.x + threadIdx.x;   // 32768 threads
    const int o = t >> 8;
    const int s = t & 255;

    float res[16];
    #pragma unroll
    for (int h_idx = 0; h_idx < 3; ++h_idx) {
        const int P    = 3 - h_idx;
        const int cnt  = (h_idx == 0) ? 6 : 5;
        const int base = (h_idx == 0) ? 0 : (h_idx == 1 ? 18 : 28);
        const int nch  = 8 * (h_idx + 1);
        const float* bb = (h_idx == 0) ? b1 : (h_idx == 1 ? b2 : b3);
        for (int jj = 0; jj < cnt; ++jj) {
            const float bias = bb[jj * 128 + o];
            float m = -1e30f;
            for (int pp = 0; pp < P; ++pp) {
                const int zmap = base + jj * P + pp;
                const float* q = g_part + ((size_t)zmap * SLOT_STRIDE) * 32768
                               + (size_t)o * 256 + s;
                float sum = 0.0f;
                #pragma unroll 8
                for (int cc = 0; cc < nch; ++cc) sum += q[(size_t)cc * 32768];
                m = fmaxf(m, sum + bias);
            }
            res[h_idx + 3 * jj] = fmaxf(m, 0.0f);
        }
    }

    float4* po = reinterpret_cast<float4*>(out + ((size_t)o * 256 + s) * 16);
    po[0] = make_float4(res[0],  res[1],  res[2],  res[3]);
    po[1] = make_float4(res[4],  res[5],  res[6],  res[7]);
    po[2] = make_float4(res[8],  res[9],  res[10], res[11]);
    po[3] = make_float4(res[12], res[13], res[14], res[15]);
}

// ---------------------------------------------------------------------------
extern "C" void kernel_launch(void* const* d_in, const int* in_sizes, int n_in,
                              void* d_out, int out_size) {
    const float* Ec = (const float*)d_in[0];
    const float* W1 = (const float*)d_in[1];
    const float* W2 = (const float*)d_in[2];
    const float* W3 = (const float*)d_in[3];
    const float* b1 = (const float*)d_in[4];
    const float* b2 = (const float*)d_in[5];
    const float* b3 = (const float*)d_in[6];
    float* out = (float*)d_out;

    cudaFuncSetAttribute(vrtconv_gemm,
                         cudaFuncAttributeMaxDynamicSharedMemorySize, SMEM_BYTES);
    vrtconv_gemm<<<424, NTHREADS, SMEM_BYTES>>>(Ec, W1, W2, W3);

    vrtconv_finish<<<128, 256>>>(b1, b2, b3, out);
}

// round 13
// speedup vs baseline: 1.7475x; 1.7192x over previous
#include <cuda_runtime.h>
#include <cuda_fp16.h>
#include <cstdint>

// ---------------------------------------------------------------------------
// Problem:
//   Ec : (128 chan, 256 s, 3 l, 128 d) f32
//   W1 : (6,128,128,1,128)  W2 : (5,128,128,2,128)  W3 : (5,128,128,3,128)
//   b1 : (6,128) b2 : (5,128) b3 : (5,128)
//   out: (128 o, 256 s, 1, 16 k) f32
// 33 conv maps: z<18 -> h=1 (kl=z/3, p=z%3); z<28 -> h=2; else h=3.
// GEMM per map: out[o,s] = sum_{a,c,d} Ec[a,s,p+c,d] * W[kl,o,a,c,d]
//   M=256(s), N=128(o), K=128*h*128.
// R12 = R9 GEMM verbatim (best GEMM: ~184us measured by subtraction) +
// two-stage reduce (high-occupancy chunk-sum + tiny finish) instead of the
// 45us latency-bound fused reduce.
// Warps 0-7: MMA (cp.async fp16 A from g_ecH, ldmatrix, mma.sync f32-acc).
// Warps 8-9: B producers (LDG.128 f32 W -> cvt fp16 -> STS), W read once.
// ---------------------------------------------------------------------------

#define NMAPS 33
#define SLOT_STRIDE 24            // max chunks per map = 8*h <= 24
__device__ __half g_ecH[12582912];                      // Ec fp16 (25 MB)
__device__ float  g_part[NMAPS * SLOT_STRIDE * 32768];  // split-K partials
__device__ float  g_sum[NMAPS * 32768];                 // per-map summed conv

#define PITCH 144                 // smem row pitch: 128B fp16 data + 16B pad
#define OFF_A 0                   // A: 256 rows (s)
#define OFF_B (256 * PITCH)       // B: 128 rows (o)
#define STAGE_BYTES (384 * PITCH) // 55296
#define NSTAGE 3
#define SMEM_BYTES (NSTAGE * STAGE_BYTES)      // 165888
#define NTHREADS 320              // 8 consumer warps + 2 producer warps
#define NST 32                    // k64 stages per K=2048 chunk

// ---------------------------------------------------------------------------
__device__ __forceinline__ uint32_t smem_u32(const void* p) {
    uint32_t r;
    asm("{ .reg .u64 t; cvta.to.shared.u64 t, %1; cvt.u32.u64 %0, t; }"
        : "=r"(r) : "l"(p));
    return r;
}

__device__ __forceinline__ void ldm4(uint32_t (&r)[4], uint32_t addr) {
    asm volatile("ldmatrix.sync.aligned.m8n8.x4.shared.b16 {%0,%1,%2,%3}, [%4];"
        : "=r"(r[0]), "=r"(r[1]), "=r"(r[2]), "=r"(r[3]) : "r"(addr));
}

__device__ __forceinline__ void mma_fp16(float (&d)[4], const uint32_t (&a)[4],
                                         uint32_t b0, uint32_t b1) {
    asm volatile(
        "mma.sync.aligned.m16n8k16.row.col.f32.f16.f16.f32 "
        "{%0,%1,%2,%3}, {%4,%5,%6,%7}, {%8,%9}, {%0,%1,%2,%3};"
        : "+f"(d[0]), "+f"(d[1]), "+f"(d[2]), "+f"(d[3])
        : "r"(a[0]), "r"(a[1]), "r"(a[2]), "r"(a[3]), "r"(b0), "r"(b1));
}

__device__ __forceinline__ void cpa16(uint32_t dst, const void* src) {
    asm volatile("cp.async.cg.shared.global [%0], [%1], 16;"
        :: "r"(dst), "l"(src));
}
#define CPA_COMMIT() asm volatile("cp.async.commit_group;" ::: "memory")
#define CPA_WAIT1()  asm volatile("cp.async.wait_group 1;"  ::: "memory")

// f32x4 -> fp16x4 (8 bytes)
__device__ __forceinline__ uint2 cvt4(float4 v) {
    __half2 h01 = __floats2half2_rn(v.x, v.y);
    __half2 h23 = __floats2half2_rn(v.z, v.w);
    uint2 r;
    r.x = *reinterpret_cast<uint32_t*>(&h01);
    r.y = *reinterpret_cast<uint32_t*>(&h23);
    return r;
}

// ---------------------------------------------------------------------------
// Ec f32 -> fp16 (one small pass; A is reused by all 33 maps)
// ---------------------------------------------------------------------------
__global__ void vrtconv_cvt_ec(const float4* __restrict__ src, int n4)
{
    uint2* dst = reinterpret_cast<uint2*>(g_ecH);
    for (int i = blockIdx.x * blockDim.x + threadIdx.x; i < n4;
         i += gridDim.x * blockDim.x)
        dst[i] = cvt4(src[i]);
}

// ---------------------------------------------------------------------------
// GEMM: grid(424). One CTA = one map z, one K-chunk of 16 (a,c) pairs
// (K=2048), full M=256(s), full N=128(o). 32 stages of k64, 3-buffer ring.
// Consumers (warps 0-7): warp tile 64x64, cp.async A feed.
// Producers (warps 8-9): stage-ahead B feed (LDG.128 f32 + cvt + STS).
// ---------------------------------------------------------------------------
__global__ __launch_bounds__(NTHREADS, 1)
void vrtconv_gemm(const float* __restrict__ W1, const float* __restrict__ W2,
                  const float* __restrict__ W3)
{
    extern __shared__ char smem[];
    const int tid  = threadIdx.x;
    const int lane = tid & 31;
    const int wid  = tid >> 5;
    const bool consumer = (wid < 8);
    const uint32_t sb = smem_u32(smem);

    // job decode: j -> (z, chunk, h)
    const int j = blockIdx.x;
    int z, chunk, h;
    if (j < 144)      { z = j >> 3;                  chunk = j & 7;    h = 1; }
    else if (j < 304) { int t = j - 144; z = 18 + (t >> 4); chunk = t & 15; h = 2; }
    else              { int t = j - 304; z = 28 + t / 24;   chunk = t % 24; h = 3; }

    int kl, p; const float* W;
    if (h == 1)      { kl = z / 3;         p = z % 3;        W = W1; }
    else if (h == 2) { kl = (z - 18) >> 1; p = (z - 18) & 1; W = W2; }
    else             { kl = z - 28;        p = 0;            W = W3; }

    const size_t oStride = (size_t)16384 * h;        // o-stride in W (f32)
    const float* Wk = W + (size_t)kl * 2097152 * (size_t)h;
    const __half* ecH = g_ecH;

    if (consumer) {
        // ---------------- consumer warps: MMA pipeline --------------------
        const int wm = wid & 3;      // 4 m-warps (64 s each)
        const int wn = wid >> 2;     // 2 n-warps (64 o each)

        float acc[4][8][4];
        #pragma unroll
        for (int a = 0; a < 4; ++a)
            #pragma unroll
            for (int b = 0; b < 8; ++b)
                #pragma unroll
                for (int c = 0; c < 4; ++c) acc[a][b][c] = 0.0f;

        // stage st: pair q = chunk*16 + (st>>1), d-block d0 = (st&1)*64
        auto cpaA = [&](int st) {
            const int q = chunk * 16 + (st >> 1);
            int a, cl;
            if (h == 1)      { a = q;      cl = 0;     }
            else if (h == 2) { a = q >> 1; cl = q & 1; }
            else             { a = q / 3;  cl = q % 3; }
            const int d0 = (st & 1) * 64;
            const __half* src = ecH + (size_t)a * 98304
                              + (size_t)(p + cl) * 128 + d0;
            const uint32_t sa = sb + (uint32_t)((st % 3) * STAGE_BYTES) + OFF_A;
            #pragma unroll
            for (int i = 0; i < 8; ++i) {          // 256 rows x 8 x 16B
                const int flat = i * 256 + tid;
                const int row = flat >> 3, c = flat & 7;
                cpa16(sa + row * PITCH + c * 16,
                      src + (size_t)row * 384 + c * 8);
            }
        };

        const uint32_t aByte = (uint32_t)((wm * 64 + (lane & 15)) * PITCH
                                          + (lane >> 4) * 16);
        const uint32_t bByte = (uint32_t)((wn * 64 + (lane & 15)) * PITCH
                                          + (lane >> 4) * 16);

        cpaA(0); CPA_COMMIT();
        cpaA(1); CPA_COMMIT();

        for (int st = 0; st < NST; ++st) {
            CPA_WAIT1();
            __syncthreads();                       // stage st (A & B) ready

            const uint32_t bufb = sb + (uint32_t)((st % 3) * STAGE_BYTES);
            #pragma unroll
            for (int kk = 0; kk < 4; ++kk) {       // k64 = 4 x k16
                uint32_t af[4][4], bf[4][4];
                #pragma unroll
                for (int mt = 0; mt < 4; ++mt)
                    ldm4(af[mt], bufb + OFF_A + aByte + mt * (16 * PITCH) + kk * 32);
                #pragma unroll
                for (int nj = 0; nj < 4; ++nj)
                    ldm4(bf[nj], bufb + OFF_B + bByte + nj * (16 * PITCH) + kk * 32);
                #pragma unroll
                for (int mt = 0; mt < 4; ++mt)
                    #pragma unroll
                    for (int nj = 0; nj < 4; ++nj) {
                        mma_fp16(acc[mt][nj * 2],     af[mt], bf[nj][0], bf[nj][2]);
                        mma_fp16(acc[mt][nj * 2 + 1], af[mt], bf[nj][1], bf[nj][3]);
                    }
            }

            if (st + 2 < NST) cpaA(st + 2);
            CPA_COMMIT();
        }

        // epilogue: partials [map][chunk][o:128][s:256]
        float* dst = g_part + ((size_t)z * SLOT_STRIDE + chunk) * 32768;
        #pragma unroll
        for (int mt = 0; mt < 4; ++mt) {
            const int s0 = wm * 64 + mt * 16 + (lane >> 2);
            #pragma unroll
            for (int n8 = 0; n8 < 8; ++n8) {
                const int o = wn * 64 + n8 * 8 + (lane & 3) * 2;
                dst[(size_t)o * 256 + s0]           = acc[mt][n8][0];
                dst[(size_t)(o + 1) * 256 + s0]     = acc[mt][n8][1];
                dst[(size_t)o * 256 + s0 + 8]       = acc[mt][n8][2];
                dst[(size_t)(o + 1) * 256 + s0 + 8] = acc[mt][n8][3];
            }
        }
    } else {
        // ---------------- producer warps: B feed (f32 -> fp16) ------------
        const int ptid = tid - 256;               // 0..63
        float4 bs[2][16];                          // two 16-float4 batches

        // load stage st's B (128 rows x 64 f32 = 2048 float4, 32/thread)
        auto ldgB = [&](int st) {
            const int q  = chunk * 16 + (st >> 1);
            const int d0 = (st & 1) * 64;
            const float* src = Wk + (size_t)q * 128 + d0;
            #pragma unroll
            for (int hf = 0; hf < 2; ++hf)
                #pragma unroll
                for (int i = 0; i < 16; ++i) {
                    const int flat = hf * 1024 + i * 64 + ptid;
                    const int row = flat >> 4, c4 = flat & 15;
                    bs[hf][i] = *reinterpret_cast<const float4*>(
                        src + (size_t)row * oStride + c4 * 4);
                }
        };
        auto stsB = [&](int st) {
            char* base = smem + (st % 3) * STAGE_BYTES + OFF_B;
            #pragma unroll
            for (int hf = 0; hf < 2; ++hf)
                #pragma unroll
                for (int i = 0; i < 16; ++i) {
                    const int flat = hf * 1024 + i * 64 + ptid;
                    const int row = flat >> 4, c4 = flat & 15;
                    *reinterpret_cast<uint2*>(base + row * PITCH + c4 * 8)
                        = cvt4(bs[hf][i]);
                }
        };

        // prologue: stage 0 fully staged before first barrier
        ldgB(0);
        stsB(0);

        for (int st = 0; st < NST; ++st) {
            __syncthreads();                       // pairs with consumer barrier
            if (st + 1 < NST) {                    // produce stage st+1
                ldgB(st + 1);
                stsB(st + 1);
            }
        }
    }
}

// ---------------------------------------------------------------------------
// Reduce stage 1: sum the 8h chunks of each map -> g_sum[map][o][s]
// grid(1056) x 256: 32 blocks per map, float4 over s. High occupancy.
// ---------------------------------------------------------------------------
__global__ void vrtconv_sum()
{
    const int map = blockIdx.x >> 5;
    const int idx = (blockIdx.x & 31) * 256 + threadIdx.x;  // 0..8191
    const int o   = idx >> 6;
    const int s4  = (idx & 63) << 2;
    const int h   = (map < 18) ? 1 : (map < 28) ? 2 : 3;
    const int nch = 8 * h;

    const float* q = g_part + (size_t)map * SLOT_STRIDE * 32768
                   + (size_t)o * 256 + s4;
    float4 acc = make_float4(0.f, 0.f, 0.f, 0.f);
    for (int cc = 0; cc < nch; ++cc) {
        float4 v = *reinterpret_cast<const float4*>(q + (size_t)cc * 32768);
        acc.x += v.x; acc.y += v.y; acc.z += v.z; acc.w += v.w;
    }
    *reinterpret_cast<float4*>(g_sum + (size_t)map * 32768
                               + (size_t)o * 256 + s4) = acc;
}

// ---------------------------------------------------------------------------
// Reduce stage 2: + bias, max over p, ReLU, write (o, s, 1, 16)
// ---------------------------------------------------------------------------
__global__ void vrtconv_finish(const float* __restrict__ b1,
                               const float* __restrict__ b2,
                               const float* __restrict__ b3,
                               float* __restrict__ out)
{
    const int t = blockIdx.x * blockDim.x + threadIdx.x;   // 32768 threads
    const int o = t >> 8;
    const int s = t & 255;

    float res[16];
    #pragma unroll
    for (int h_idx = 0; h_idx < 3; ++h_idx) {
        const int P    = 3 - h_idx;
        const int cnt  = (h_idx == 0) ? 6 : 5;
        const int base = (h_idx == 0) ? 0 : (h_idx == 1 ? 18 : 28);
        const float* bb = (h_idx == 0) ? b1 : (h_idx == 1 ? b2 : b3);
        for (int jj = 0; jj < cnt; ++jj) {
            const float bias = bb[jj * 128 + o];
            float m = -1e30f;
            for (int pp = 0; pp < P; ++pp) {
                const int zmap = base + jj * P + pp;
                m = fmaxf(m, g_sum[(size_t)zmap * 32768 + (size_t)o * 256 + s] + bias);
            }
            res[h_idx + 3 * jj] = fmaxf(m, 0.0f);
        }
    }

    float4* po = reinterpret_cast<float4*>(out + ((size_t)o * 256 + s) * 16);
    po[0] = make_float4(res[0],  res[1],  res[2],  res[3]);
    po[1] = make_float4(res[4],  res[5],  res[6],  res[7]);
    po[2] = make_float4(res[8],  res[9],  res[10], res[11]);
    po[3] = make_float4(res[12], res[13], res[14], res[15]);
}

// ---------------------------------------------------------------------------
extern "C" void kernel_launch(void* const* d_in, const int* in_sizes, int n_in,
                              void* d_out, int out_size) {
    const float* Ec = (const float*)d_in[0];
    const float* W1 = (const float*)d_in[1];
    const float* W2 = (const float*)d_in[2];
    const float* W3 = (const float*)d_in[3];
    const float* b1 = (const float*)d_in[4];
    const float* b2 = (const float*)d_in[5];
    const float* b3 = (const float*)d_in[6];
    float* out = (float*)d_out;

    vrtconv_cvt_ec<<<1536, 256>>>((const float4*)Ec, 12582912 / 4);

    cudaFuncSetAttribute(vrtconv_gemm,
                         cudaFuncAttributeMaxDynamicSharedMemorySize, SMEM_BYTES);
    vrtconv_gemm<<<424, NTHREADS, SMEM_BYTES>>>(W1, W2, W3);

    vrtconv_sum<<<1056, 256>>>();
    vrtconv_finish<<<128, 256>>>(b1, b2, b3, out);
}

// round 14
// speedup vs baseline: 1.7797x; 1.0184x over previous
#include <cuda_runtime.h>
#include <cuda_fp16.h>
#include <cstdint>

// ---------------------------------------------------------------------------
// Problem:
//   Ec : (128 chan, 256 s, 3 l, 128 d) f32
//   W1 : (6,128,128,1,128)  W2 : (5,128,128,2,128)  W3 : (5,128,128,3,128)
//   b1 : (6,128) b2 : (5,128) b3 : (5,128)
//   out: (128 o, 256 s, 1, 16 k) f32
// 33 conv maps: z<18 -> h=1 (kl=z/3, p=z%3); z<28 -> h=2; else h=3.
// GEMM per map: out[o,s] = sum_{a,c,d} Ec[a,s,p+c,d] * W[kl,o,a,c,d]
//   M=256(s), N=128(o), K=128*h*128.
// R13 = R12 GEMM byte-identical (at legacy mma.sync floor, ~184us) +
//   (1) single-pass high-parallelism reduce (block=(o,k), 524K threads)
//   (2) cvt_ec with uint4 stores.
// Warps 0-7: MMA (cp.async fp16 A from g_ecH, ldmatrix, mma.sync f32-acc).
// Warps 8-9: B producers (LDG.128 f32 W -> cvt fp16 -> STS), W read once.
// ---------------------------------------------------------------------------

#define NMAPS 33
#define SLOT_STRIDE 24            // max chunks per map = 8*h <= 24
__device__ __half g_ecH[12582912];                      // Ec fp16 (25 MB)
__device__ float  g_part[NMAPS * SLOT_STRIDE * 32768];  // split-K partials

#define PITCH 144                 // smem row pitch: 128B fp16 data + 16B pad
#define OFF_A 0                   // A: 256 rows (s)
#define OFF_B (256 * PITCH)       // B: 128 rows (o)
#define STAGE_BYTES (384 * PITCH) // 55296
#define NSTAGE 3
#define SMEM_BYTES (NSTAGE * STAGE_BYTES)      // 165888
#define NTHREADS 320              // 8 consumer warps + 2 producer warps
#define NST 32                    // k64 stages per K=2048 chunk

// ---------------------------------------------------------------------------
__device__ __forceinline__ uint32_t smem_u32(const void* p) {
    uint32_t r;
    asm("{ .reg .u64 t; cvta.to.shared.u64 t, %1; cvt.u32.u64 %0, t; }"
        : "=r"(r) : "l"(p));
    return r;
}

__device__ __forceinline__ void ldm4(uint32_t (&r)[4], uint32_t addr) {
    asm volatile("ldmatrix.sync.aligned.m8n8.x4.shared.b16 {%0,%1,%2,%3}, [%4];"
        : "=r"(r[0]), "=r"(r[1]), "=r"(r[2]), "=r"(r[3]) : "r"(addr));
}

__device__ __forceinline__ void mma_fp16(float (&d)[4], const uint32_t (&a)[4],
                                         uint32_t b0, uint32_t b1) {
    asm volatile(
        "mma.sync.aligned.m16n8k16.row.col.f32.f16.f16.f32 "
        "{%0,%1,%2,%3}, {%4,%5,%6,%7}, {%8,%9}, {%0,%1,%2,%3};"
        : "+f"(d[0]), "+f"(d[1]), "+f"(d[2]), "+f"(d[3])
        : "r"(a[0]), "r"(a[1]), "r"(a[2]), "r"(a[3]), "r"(b0), "r"(b1));
}

__device__ __forceinline__ void cpa16(uint32_t dst, const void* src) {
    asm volatile("cp.async.cg.shared.global [%0], [%1], 16;"
        :: "r"(dst), "l"(src));
}
#define CPA_COMMIT() asm volatile("cp.async.commit_group;" ::: "memory")
#define CPA_WAIT1()  asm volatile("cp.async.wait_group 1;"  ::: "memory")

// f32x4 -> fp16x4 (8 bytes)
__device__ __forceinline__ uint2 cvt4(float4 v) {
    __half2 h01 = __floats2half2_rn(v.x, v.y);
    __half2 h23 = __floats2half2_rn(v.z, v.w);
    uint2 r;
    r.x = *reinterpret_cast<uint32_t*>(&h01);
    r.y = *reinterpret_cast<uint32_t*>(&h23);
    return r;
}

// ---------------------------------------------------------------------------
// Ec f32 -> fp16: 8 floats/thread/iter, uint4 stores.
// ---------------------------------------------------------------------------
__global__ void vrtconv_cvt_ec(const float4* __restrict__ src, int n8)
{
    uint4* dst = reinterpret_cast<uint4*>(g_ecH);
    for (int i = blockIdx.x * blockDim.x + threadIdx.x; i < n8;
         i += gridDim.x * blockDim.x) {
        float4 a = src[2 * i];
        float4 b = src[2 * i + 1];
        uint2 ra = cvt4(a);
        uint2 rb = cvt4(b);
        uint4 r; r.x = ra.x; r.y = ra.y; r.z = rb.x; r.w = rb.y;
        dst[i] = r;
    }
}

// ---------------------------------------------------------------------------
// GEMM: grid(424). One CTA = one map z, one K-chunk of 16 (a,c) pairs
// (K=2048), full M=256(s), full N=128(o). 32 stages of k64, 3-buffer ring.
// Consumers (warps 0-7): warp tile 64x64, cp.async A feed.
// Producers (warps 8-9): stage-ahead B feed (LDG.128 f32 + cvt + STS).
// ---------------------------------------------------------------------------
__global__ __launch_bounds__(NTHREADS, 1)
void vrtconv_gemm(const float* __restrict__ W1, const float* __restrict__ W2,
                  const float* __restrict__ W3)
{
    extern __shared__ char smem[];
    const int tid  = threadIdx.x;
    const int lane = tid & 31;
    const int wid  = tid >> 5;
    const bool consumer = (wid < 8);
    const uint32_t sb = smem_u32(smem);

    // job decode: j -> (z, chunk, h)
    const int j = blockIdx.x;
    int z, chunk, h;
    if (j < 144)      { z = j >> 3;                  chunk = j & 7;    h = 1; }
    else if (j < 304) { int t = j - 144; z = 18 + (t >> 4); chunk = t & 15; h = 2; }
    else              { int t = j - 304; z = 28 + t / 24;   chunk = t % 24; h = 3; }

    int kl, p; const float* W;
    if (h == 1)      { kl = z / 3;         p = z % 3;        W = W1; }
    else if (h == 2) { kl = (z - 18) >> 1; p = (z - 18) & 1; W = W2; }
    else             { kl = z - 28;        p = 0;            W = W3; }

    const size_t oStride = (size_t)16384 * h;        // o-stride in W (f32)
    const float* Wk = W + (size_t)kl * 2097152 * (size_t)h;
    const __half* ecH = g_ecH;

    if (consumer) {
        // ---------------- consumer warps: MMA pipeline --------------------
        const int wm = wid & 3;      // 4 m-warps (64 s each)
        const int wn = wid >> 2;     // 2 n-warps (64 o each)

        float acc[4][8][4];
        #pragma unroll
        for (int a = 0; a < 4; ++a)
            #pragma unroll
            for (int b = 0; b < 8; ++b)
                #pragma unroll
                for (int c = 0; c < 4; ++c) acc[a][b][c] = 0.0f;

        // stage st: pair q = chunk*16 + (st>>1), d-block d0 = (st&1)*64
        auto cpaA = [&](int st) {
            const int q = chunk * 16 + (st >> 1);
            int a, cl;
            if (h == 1)      { a = q;      cl = 0;     }
            else if (h == 2) { a = q >> 1; cl = q & 1; }
            else             { a = q / 3;  cl = q % 3; }
            const int d0 = (st & 1) * 64;
            const __half* src = ecH + (size_t)a * 98304
                              + (size_t)(p + cl) * 128 + d0;
            const uint32_t sa = sb + (uint32_t)((st % 3) * STAGE_BYTES) + OFF_A;
            #pragma unroll
            for (int i = 0; i < 8; ++i) {          // 256 rows x 8 x 16B
                const int flat = i * 256 + tid;
                const int row = flat >> 3, c = flat & 7;
                cpa16(sa + row * PITCH + c * 16,
                      src + (size_t)row * 384 + c * 8);
            }
        };

        const uint32_t aByte = (uint32_t)((wm * 64 + (lane & 15)) * PITCH
                                          + (lane >> 4) * 16);
        const uint32_t bByte = (uint32_t)((wn * 64 + (lane & 15)) * PITCH
                                          + (lane >> 4) * 16);

        cpaA(0); CPA_COMMIT();
        cpaA(1); CPA_COMMIT();

        for (int st = 0; st < NST; ++st) {
            CPA_WAIT1();
            __syncthreads();                       // stage st (A & B) ready

            const uint32_t bufb = sb + (uint32_t)((st % 3) * STAGE_BYTES);
            #pragma unroll
            for (int kk = 0; kk < 4; ++kk) {       // k64 = 4 x k16
                uint32_t af[4][4], bf[4][4];
                #pragma unroll
                for (int mt = 0; mt < 4; ++mt)
                    ldm4(af[mt], bufb + OFF_A + aByte + mt * (16 * PITCH) + kk * 32);
                #pragma unroll
                for (int nj = 0; nj < 4; ++nj)
                    ldm4(bf[nj], bufb + OFF_B + bByte + nj * (16 * PITCH) + kk * 32);
                #pragma unroll
                for (int mt = 0; mt < 4; ++mt)
                    #pragma unroll
                    for (int nj = 0; nj < 4; ++nj) {
                        mma_fp16(acc[mt][nj * 2],     af[mt], bf[nj][0], bf[nj][2]);
                        mma_fp16(acc[mt][nj * 2 + 1], af[mt], bf[nj][1], bf[nj][3]);
                    }
            }

            if (st + 2 < NST) cpaA(st + 2);
            CPA_COMMIT();
        }

        // epilogue: partials [map][chunk][o:128][s:256]
        float* dst = g_part + ((size_t)z * SLOT_STRIDE + chunk) * 32768;
        #pragma unroll
        for (int mt = 0; mt < 4; ++mt) {
            const int s0 = wm * 64 + mt * 16 + (lane >> 2);
            #pragma unroll
            for (int n8 = 0; n8 < 8; ++n8) {
                const int o = wn * 64 + n8 * 8 + (lane & 3) * 2;
                dst[(size_t)o * 256 + s0]           = acc[mt][n8][0];
                dst[(size_t)(o + 1) * 256 + s0]     = acc[mt][n8][1];
                dst[(size_t)o * 256 + s0 + 8]       = acc[mt][n8][2];
                dst[(size_t)(o + 1) * 256 + s0 + 8] = acc[mt][n8][3];
            }
        }
    } else {
        // ---------------- producer warps: B feed (f32 -> fp16) ------------
        const int ptid = tid - 256;               // 0..63
        float4 bs[2][16];                          // two 16-float4 batches

        // load stage st's B (128 rows x 64 f32 = 2048 float4, 32/thread)
        auto ldgB = [&](int st) {
            const int q  = chunk * 16 + (st >> 1);
            const int d0 = (st & 1) * 64;
            const float* src = Wk + (size_t)q * 128 + d0;
            #pragma unroll
            for (int hf = 0; hf < 2; ++hf)
                #pragma unroll
                for (int i = 0; i < 16; ++i) {
                    const int flat = hf * 1024 + i * 64 + ptid;
                    const int row = flat >> 4, c4 = flat & 15;
                    bs[hf][i] = *reinterpret_cast<const float4*>(
                        src + (size_t)row * oStride + c4 * 4);
                }
        };
        auto stsB = [&](int st) {
            char* base = smem + (st % 3) * STAGE_BYTES + OFF_B;
            #pragma unroll
            for (int hf = 0; hf < 2; ++hf)
                #pragma unroll
                for (int i = 0; i < 16; ++i) {
                    const int flat = hf * 1024 + i * 64 + ptid;
                    const int row = flat >> 4, c4 = flat & 15;
                    *reinterpret_cast<uint2*>(base + row * PITCH + c4 * 8)
                        = cvt4(bs[hf][i]);
                }
        };

        // prologue: stage 0 fully staged before first barrier
        ldgB(0);
        stsB(0);

        for (int st = 0; st < NST; ++st) {
            __syncthreads();                       // pairs with consumer barrier
            if (st + 1 < NST) {                    // produce stage st+1
                ldgB(st + 1);
                stsB(st + 1);
            }
        }
    }
}

// ---------------------------------------------------------------------------
// Single-pass reduce: block = (o, k). 2048 blocks x 256 threads (thread = s).
// Each thread: sum 8h chunks for each of P maps, + bias, max, ReLU, store.
// All g_part reads coalesced in s; each partial read exactly once.
// ---------------------------------------------------------------------------
__global__ void vrtconv_reduce(const float* __restrict__ b1,
                               const float* __restrict__ b2,
                               const float* __restrict__ b3,
                               float* __restrict__ out)
{
    const int o = blockIdx.x >> 4;
    const int k = blockIdx.x & 15;
    const int s = threadIdx.x;

    const int h_idx = k % 3;       // k = h_idx + 3*jj
    const int jj    = k / 3;
    const int P     = 3 - h_idx;
    const int base  = (h_idx == 0) ? 0 : (h_idx == 1 ? 18 : 28);
    const int nch   = 8 * (h_idx + 1);
    const float* bb = (h_idx == 0) ? b1 : (h_idx == 1 ? b2 : b3);
    const float bias = bb[jj * 128 + o];

    float m = -1e30f;
    for (int pp = 0; pp < P; ++pp) {
        const int zmap = base + jj * P + pp;
        const float* q = g_part + (size_t)zmap * SLOT_STRIDE * 32768
                       + (size_t)o * 256 + s;
        float sum = 0.0f;
        #pragma unroll 8
        for (int cc = 0; cc < nch; ++cc) sum += q[(size_t)cc * 32768];
        m = fmaxf(m, sum + bias);
    }
    out[((size_t)o * 256 + s) * 16 + k] = fmaxf(m, 0.0f);
}

// ---------------------------------------------------------------------------
extern "C" void kernel_launch(void* const* d_in, const int* in_sizes, int n_in,
                              void* d_out, int out_size) {
    const float* Ec = (const float*)d_in[0];
    const float* W1 = (const float*)d_in[1];
    const float* W2 = (const float*)d_in[2];
    const float* W3 = (const float*)d_in[3];
    const float* b1 = (const float*)d_in[4];
    const float* b2 = (const float*)d_in[5];
    const float* b3 = (const float*)d_in[6];
    float* out = (float*)d_out;

    vrtconv_cvt_ec<<<1536, 256>>>((const float4*)Ec, 12582912 / 8);

    cudaFuncSetAttribute(vrtconv_gemm,
                         cudaFuncAttributeMaxDynamicSharedMemorySize, SMEM_BYTES);
    vrtconv_gemm<<<424, NTHREADS, SMEM_BYTES>>>(W1, W2, W3);

    vrtconv_reduce<<<2048, 256>>>(b1, b2, b3, out);
}